// round 4
// baseline (speedup 1.0000x reference)
#include <cuda_runtime.h>

#define BATCH   262144
#define T_STEPS 20
#define BETAF   0.9f
#define THRESHF 1.0f

using u32 = unsigned int;
using u64 = unsigned long long;

__device__ __forceinline__ u64 pack2(float lo, float hi) {
    u64 r; asm("mov.b64 %0, {%1, %2};" : "=l"(r) : "f"(lo), "f"(hi)); return r;
}
__device__ __forceinline__ void unpack2(u64 v, float &lo, float &hi) {
    asm("mov.b64 {%0, %1}, %2;" : "=f"(lo), "=f"(hi) : "l"(v));
}
__device__ __forceinline__ u64 ffma2(u64 a, u64 b, u64 c) {
    u64 d; asm("fma.rn.f32x2 %0, %1, %2, %3;" : "=l"(d) : "l"(a), "l"(b), "l"(c)); return d;
}
// Predicated packed adds: acc += w iff cond != 0. Exactly matches fma(s,w,acc) for s in {0,1}.
__device__ __forceinline__ void padd2(u64 &a0, u64 &a1, u32 cond, u64 w0, u64 w1) {
    asm("{ .reg .pred p; setp.ne.u32 p, %4, 0;\n\t"
        "@p add.rn.f32x2 %0, %0, %2;\n\t"
        "@p add.rn.f32x2 %1, %1, %3; }"
        : "+l"(a0), "+l"(a1) : "l"(w0), "l"(w1), "r"(cond));
}
__device__ __forceinline__ void padd1(u64 &a0, u32 cond, u64 w0) {
    asm("{ .reg .pred p; setp.ne.u32 p, %2, 0;\n\t"
        "@p add.rn.f32x2 %0, %0, %1; }"
        : "+l"(a0) : "l"(w0), "r"(cond));
}

// ---- static smem weights, eighth-major pair-packed ----
// w[(i*8 + oct)*P4 + p] = (W[O*oct + 2p][i], W[O*oct + 2p + 1][i]),  O = 2*P4
__shared__ u64 sW1[10 * 8 * 4];  // 10 -> 64, P4=4
__shared__ u64 sW2[64 * 8 * 2];  // 64 -> 32, P4=2
__shared__ u64 sW3[32 * 8 * 2];  // 32 -> 32, P4=2
__shared__ u64 sW4[32 * 8 * 1];  // 32 -> 16, P4=1
__shared__ u64 sW5[16 * 8 * 1];  // 16 -> 6 (padded to 16 outs), P4=1

__device__ __forceinline__ void stage(u64* dst, const float* __restrict__ W,
                                      int NIN, int NOUT, int P4, int tid, int nthr) {
    int total = NIN * 8 * P4;
    for (int idx = tid; idx < total; idx += nthr) {
        int i = idx / (8 * P4);
        int r = idx % (8 * P4);
        int o = r / P4, p = r % P4;
        int j0 = 2 * (o * P4 + p);
        float a = (j0     < NOUT) ? W[j0 * NIN + i]       : 0.0f;
        float b = (j0 + 1 < NOUT) ? W[(j0 + 1) * NIN + i] : 0.0f;
        dst[idx] = pack2(a, b);
    }
}

// LIF for one output pair; returns 2-bit spike mask. Same formula/order as prior rounds.
__device__ __forceinline__ u32 lif_pair(u64 acc, float &mA, float &mB) {
    float a0, a1; unpack2(acc, a0, a1);
    float r0 = mA > THRESHF ? THRESHF : 0.0f;
    float r1 = mB > THRESHF ? THRESHF : 0.0f;
    mA = fmaf(BETAF, mA, a0 - r0);
    mB = fmaf(BETAF, mB, a1 - r1);
    u32 m = 0;
    if (mA > THRESHF) m |= 1u;
    if (mB > THRESHF) m |= 2u;
    return m;
}

// Butterfly-OR across the 8-lane oct group (d = 1,2,4). Inputs occupy disjoint
// bit ranges per oct, so OR accumulates the full mask into every lane.
__device__ __forceinline__ u32 bfly_or(u32 v) {
    v |= __shfl_xor_sync(0xffffffffu, v, 1);
    v |= __shfl_xor_sync(0xffffffffu, v, 2);
    v |= __shfl_xor_sync(0xffffffffu, v, 4);
    return v;
}

__global__ __launch_bounds__(128) void lif_kernel(
    const float* __restrict__ x,
    const float* __restrict__ W1, const float* __restrict__ W2,
    const float* __restrict__ W3, const float* __restrict__ W4,
    const float* __restrict__ W5, float* __restrict__ out)
{
    int tid = threadIdx.x;
    stage(sW1, W1, 10, 64, 4, tid, 128);
    stage(sW2, W2, 64, 32, 2, tid, 128);
    stage(sW3, W3, 32, 32, 2, tid, 128);
    stage(sW4, W4, 32, 16, 1, tid, 128);
    stage(sW5, W5, 16,  6, 1, tid, 128);
    __syncthreads();

    const int oct  = tid & 7;            // eighth of each layer's outputs
    const int slot = tid >> 3;           // 16 slots per block, 4 elements each
    const size_t ebase = ((size_t)blockIdx.x * 16 + slot) * 4;

    const u64* w1o = sW1 + oct * 4;      // row stride 8*4
    const u64* w2o = sW2 + oct * 2;      // row stride 8*2
    const u64* w3o = sW3 + oct * 2;
    const u64* w4o = sW4 + oct;          // row stride 8
    const u64* w5o = sW5 + oct;

    // membrane state: 19 floats per element (eighth of every layer), E=4
    float m1[4][8], m2[4][4], m3[4][4], m4[4][2], m5[4][2];
#pragma unroll
    for (int el = 0; el < 4; ++el) {
#pragma unroll
        for (int k = 0; k < 8; ++k) m1[el][k] = 0.f;
#pragma unroll
        for (int k = 0; k < 4; ++k) { m2[el][k] = 0.f; m3[el][k] = 0.f; }
#pragma unroll
        for (int k = 0; k < 2; ++k) { m4[el][k] = 0.f; m5[el][k] = 0.f; }
    }

#pragma unroll 1
    for (int t = 0; t < T_STEPS; ++t) {
        // ---- prefetch x[t, ebase+el, 0:10] ----
        float2 xv[4][5];
#pragma unroll
        for (int el = 0; el < 4; ++el) {
            const float2* xp = (const float2*)(x + ((size_t)t * BATCH + ebase + el) * 10);
#pragma unroll
            for (int i = 0; i < 5; ++i) xv[el][i] = xp[i];
        }

        // ---- Layer 1: 10 -> 64 (4 pairs per oct, real-valued inputs) ----
        u64 acc1[4][4];
#pragma unroll
        for (int el = 0; el < 4; ++el)
#pragma unroll
            for (int p = 0; p < 4; ++p) acc1[el][p] = 0ull;
#pragma unroll
        for (int i = 0; i < 10; ++i) {
            const ulonglong2* wp = (const ulonglong2*)(w1o + i * 32);
            ulonglong2 wa = wp[0], wb = wp[1];
#pragma unroll
            for (int el = 0; el < 4; ++el) {
                float xf = (i & 1) ? xv[el][i >> 1].y : xv[el][i >> 1].x;
                u64 xd = pack2(xf, xf);
                acc1[el][0] = ffma2(xd, wa.x, acc1[el][0]);
                acc1[el][1] = ffma2(xd, wa.y, acc1[el][1]);
                acc1[el][2] = ffma2(xd, wb.x, acc1[el][2]);
                acc1[el][3] = ffma2(xd, wb.y, acc1[el][3]);
            }
        }
        // LIF + build 64-bit L1 masks (2 words per element)
        u32 l1lo[4], l1hi[4];
#pragma unroll
        for (int el = 0; el < 4; ++el) {
            u32 m8 = 0;
#pragma unroll
            for (int p = 0; p < 4; ++p)
                m8 |= lif_pair(acc1[el][p], m1[el][2 * p], m1[el][2 * p + 1]) << (2 * p);
            u32 w0 = (oct < 4) ? (m8 << (oct * 8)) : 0u;
            u32 w1 = (oct >= 4) ? (m8 << ((oct - 4) * 8)) : 0u;
            l1lo[el] = bfly_or(w0);
            l1hi[el] = bfly_or(w1);
        }

        // ---- Layer 2: 64 -> 32 (2 pairs per oct, predicated adds) ----
        u64 acc2[4][2];
#pragma unroll
        for (int el = 0; el < 4; ++el) { acc2[el][0] = 0ull; acc2[el][1] = 0ull; }
#pragma unroll
        for (int i = 0; i < 64; ++i) {
            const ulonglong2* wp = (const ulonglong2*)(w2o + i * 16);
            ulonglong2 w = wp[0];
#pragma unroll
            for (int el = 0; el < 4; ++el) {
                u32 c = (i < 32) ? (l1lo[el] & (1u << i)) : (l1hi[el] & (1u << (i - 32)));
                padd2(acc2[el][0], acc2[el][1], c, w.x, w.y);
            }
        }
        u32 f2[4];
#pragma unroll
        for (int el = 0; el < 4; ++el) {
            u32 m4b = lif_pair(acc2[el][0], m2[el][0], m2[el][1])
                    | (lif_pair(acc2[el][1], m2[el][2], m2[el][3]) << 2);
            f2[el] = bfly_or(m4b << (oct * 4));
        }

        // ---- Layer 3: 32 -> 32 ----
        u64 acc3[4][2];
#pragma unroll
        for (int el = 0; el < 4; ++el) { acc3[el][0] = 0ull; acc3[el][1] = 0ull; }
#pragma unroll
        for (int i = 0; i < 32; ++i) {
            const ulonglong2* wp = (const ulonglong2*)(w3o + i * 16);
            ulonglong2 w = wp[0];
#pragma unroll
            for (int el = 0; el < 4; ++el)
                padd2(acc3[el][0], acc3[el][1], f2[el] & (1u << i), w.x, w.y);
        }
        u32 f3[4];
#pragma unroll
        for (int el = 0; el < 4; ++el) {
            u32 m4b = lif_pair(acc3[el][0], m3[el][0], m3[el][1])
                    | (lif_pair(acc3[el][1], m3[el][2], m3[el][3]) << 2);
            f3[el] = bfly_or(m4b << (oct * 4));
        }

        // ---- Layer 4: 32 -> 16 (1 pair per oct) ----
        u64 acc4[4];
#pragma unroll
        for (int el = 0; el < 4; ++el) acc4[el] = 0ull;
#pragma unroll
        for (int i = 0; i < 32; ++i) {
            u64 w = w4o[i * 8];
#pragma unroll
            for (int el = 0; el < 4; ++el)
                padd1(acc4[el], f3[el] & (1u << i), w);
        }
        u32 f4[4];
#pragma unroll
        for (int el = 0; el < 4; ++el) {
            u32 m2b = lif_pair(acc4[el], m4[el][0], m4[el][1]);
            f4[el] = bfly_or(m2b << (oct * 2));
        }

        // ---- Layer 5: 16 -> 6 (padded; 1 pair per oct, real for oct<3) ----
        u64 acc5[4];
#pragma unroll
        for (int el = 0; el < 4; ++el) acc5[el] = 0ull;
#pragma unroll
        for (int i = 0; i < 16; ++i) {
            u64 w = w5o[i * 8];
#pragma unroll
            for (int el = 0; el < 4; ++el)
                padd1(acc5[el], f4[el] & (1u << i), w);
        }
#pragma unroll
        for (int el = 0; el < 4; ++el) {
            float a0, a1; unpack2(acc5[el], a0, a1);
            float r0 = m5[el][0] > THRESHF ? THRESHF : 0.0f;
            float r1 = m5[el][1] > THRESHF ? THRESHF : 0.0f;
            float mm0 = fmaf(BETAF, m5[el][0], a0 - r0);
            float mm1 = fmaf(BETAF, m5[el][1], a1 - r1);
            m5[el][0] = mm0; m5[el][1] = mm1;
            if (oct < 3) {
                float2 o;
                o.x = mm0 > THRESHF ? 1.0f : 0.0f;
                o.y = mm1 > THRESHF ? 1.0f : 0.0f;
                *(float2*)(out + ((size_t)t * BATCH + ebase + el) * 6 + oct * 2) = o;
            }
        }
    }
}

extern "C" void kernel_launch(void* const* d_in, const int* in_sizes, int n_in,
                              void* d_out, int out_size) {
    const float *x = nullptr, *W1 = nullptr, *W2 = nullptr, *W3 = nullptr,
                *W4 = nullptr, *W5 = nullptr;
    for (int i = 0; i < n_in; ++i) {
        const float* p = (const float*)d_in[i];
        switch (in_sizes[i]) {
            case 52428800: x  = p; break;  // (20, 262144, 10)
            case 640:      W1 = p; break;  // (64, 10)
            case 2048:     W2 = p; break;  // (32, 64)
            case 1024:     W3 = p; break;  // (32, 32)
            case 512:      W4 = p; break;  // (16, 32)
            case 96:       W5 = p; break;  // (6, 16)
            default: break;
        }
    }
    float* out = (float*)d_out;
    // 8 threads per element, E=4 elements per thread: 64 elements per 128-thread block
    lif_kernel<<<BATCH / 64, 128>>>(x, W1, W2, W3, W4, W5, out);
}

// round 5
// speedup vs baseline: 1.0707x; 1.0707x over previous
#include <cuda_runtime.h>

#define BATCH   262144
#define T_STEPS 20
#define BETAF   0.9f
#define THRESHF 1.0f

using u32 = unsigned int;
using u64 = unsigned long long;

__device__ __forceinline__ u64 pack2(float lo, float hi) {
    u64 r; asm("mov.b64 %0, {%1, %2};" : "=l"(r) : "f"(lo), "f"(hi)); return r;
}
__device__ __forceinline__ void unpack2(u64 v, float &lo, float &hi) {
    asm("mov.b64 {%0, %1}, %2;" : "=f"(lo), "=f"(hi) : "l"(v));
}
__device__ __forceinline__ u64 ffma2(u64 a, u64 b, u64 c) {
    u64 d; asm("fma.rn.f32x2 %0, %1, %2, %3;" : "=l"(d) : "l"(a), "l"(b), "l"(c)); return d;
}
// One predicate (mask & bit) shared across 4 packed adds. Exact: add == fma(1,w,acc).
__device__ __forceinline__ void padd4(u64 &a0, u64 &a1, u64 &a2, u64 &a3,
                                      u32 mask, u32 bit,
                                      u64 w0, u64 w1, u64 w2, u64 w3) {
    asm("{ .reg .pred p; .reg .b32 r;\n\t"
        "and.b32 r, %8, %9; setp.ne.u32 p, r, 0;\n\t"
        "@p add.rn.f32x2 %0, %0, %4;\n\t"
        "@p add.rn.f32x2 %1, %1, %5;\n\t"
        "@p add.rn.f32x2 %2, %2, %6;\n\t"
        "@p add.rn.f32x2 %3, %3, %7; }"
        : "+l"(a0), "+l"(a1), "+l"(a2), "+l"(a3)
        : "l"(w0), "l"(w1), "l"(w2), "l"(w3), "r"(mask), "r"(bit));
}
__device__ __forceinline__ void padd2(u64 &a0, u64 &a1, u32 mask, u32 bit, u64 w0, u64 w1) {
    asm("{ .reg .pred p; .reg .b32 r;\n\t"
        "and.b32 r, %4, %5; setp.ne.u32 p, r, 0;\n\t"
        "@p add.rn.f32x2 %0, %0, %2;\n\t"
        "@p add.rn.f32x2 %1, %1, %3; }"
        : "+l"(a0), "+l"(a1) : "l"(w0), "l"(w1), "r"(mask), "r"(bit));
}
__device__ __forceinline__ void padd1(u64 &a0, u32 mask, u32 bit, u64 w0) {
    asm("{ .reg .pred p; .reg .b32 r;\n\t"
        "and.b32 r, %2, %3; setp.ne.u32 p, r, 0;\n\t"
        "@p add.rn.f32x2 %0, %0, %1; }"
        : "+l"(a0) : "l"(w0), "r"(mask), "r"(bit));
}

// ---- static smem weights, quarter-major pair-packed with bank-spread padding ----
// w[(i*4 + q)*QS + p] = (W[2*(q*P4+p)][i], W[2*(q*P4+p)+1][i])
#define QS1 10  // P4=8  : q offsets 0,80,160,240B -> banks 0-3,20-23,8-11,28-31 (LDS.128)
#define QS2 6   // P4=4  : 0,48,96,144B -> 0-3,12-15,24-27,4-7
#define QS3 6   // P4=4
#define QS4 4   // P4=2  : 0,32,64,96B  -> 0-3,8-11,16-19,24-27
#define QS5 2   // P4=1  : LDS.64, 0,16,32,48B -> 0-1,4-5,8-9,12-13
__shared__ u64 sW1[10 * 4 * QS1];
__shared__ u64 sW2[64 * 4 * QS2];
__shared__ u64 sW3[32 * 4 * QS3];
__shared__ u64 sW4[32 * 4 * QS4];
__shared__ u64 sW5[16 * 4 * QS5];

__device__ __forceinline__ void stage(u64* dst, const float* __restrict__ W,
                                      int NIN, int NOUT, int P4, int QS, int tid) {
    int total = NIN * 4 * P4;
    for (int idx = tid; idx < total; idx += 128) {
        int i = idx / (4 * P4);
        int r = idx % (4 * P4);
        int q = r / P4, p = r % P4;
        int j0 = 2 * (q * P4 + p);
        float a = (j0     < NOUT) ? W[j0 * NIN + i]       : 0.0f;
        float b = (j0 + 1 < NOUT) ? W[(j0 + 1) * NIN + i] : 0.0f;
        dst[(i * 4 + q) * QS + p] = pack2(a, b);
    }
}

// LIF for one output pair; returns 2-bit spike mask. Same formula/order as rounds 1-4.
__device__ __forceinline__ u32 lif_pair(u64 acc, float &mA, float &mB) {
    float a0, a1; unpack2(acc, a0, a1);
    float r0 = mA > THRESHF ? THRESHF : 0.0f;
    float r1 = mB > THRESHF ? THRESHF : 0.0f;
    mA = fmaf(BETAF, mA, a0 - r0);
    mB = fmaf(BETAF, mB, a1 - r1);
    u32 m = 0;
    if (mA > THRESHF) m |= 1u;
    if (mB > THRESHF) m |= 2u;
    return m;
}

// OR-reduce across the 4-lane quarter group (lane bits 0-1 = q).
__device__ __forceinline__ u32 bfly_or4(u32 v) {
    v |= __shfl_xor_sync(0xffffffffu, v, 1);
    v |= __shfl_xor_sync(0xffffffffu, v, 2);
    return v;
}

__global__ __launch_bounds__(128, 3) void lif_kernel(
    const float* __restrict__ x,
    const float* __restrict__ W1, const float* __restrict__ W2,
    const float* __restrict__ W3, const float* __restrict__ W4,
    const float* __restrict__ W5, float* __restrict__ out)
{
    int tid = threadIdx.x;
    stage(sW1, W1, 10, 64, 8, QS1, tid);
    stage(sW2, W2, 64, 32, 4, QS2, tid);
    stage(sW3, W3, 32, 32, 4, QS3, tid);
    stage(sW4, W4, 32, 16, 2, QS4, tid);
    stage(sW5, W5, 16,  6, 1, QS5, tid);
    __syncthreads();

    const int q = tid & 3;                         // quarter of each layer's outputs
    const size_t ebase = (size_t)blockIdx.x * 64 + (tid >> 2) * 2;   // 2 elements/thread

    const u64* w1q = sW1 + q * QS1;
    const u64* w2q = sW2 + q * QS2;
    const u64* w3q = sW3 + q * QS3;
    const u64* w4q = sW4 + q * QS4;
    const u64* w5q = sW5 + q * QS5;

    // membrane state: quarter of every layer, for E=2 elements (38 floats each)
    float m1[2][16], m2[2][8], m3[2][8], m4[2][4], m5[2][2];
#pragma unroll
    for (int el = 0; el < 2; ++el) {
#pragma unroll
        for (int k = 0; k < 16; ++k) m1[el][k] = 0.f;
#pragma unroll
        for (int k = 0; k < 8; ++k) { m2[el][k] = 0.f; m3[el][k] = 0.f; }
#pragma unroll
        for (int k = 0; k < 4; ++k)  m4[el][k] = 0.f;
#pragma unroll
        for (int k = 0; k < 2; ++k)  m5[el][k] = 0.f;
    }

#pragma unroll 1
    for (int t = 0; t < T_STEPS; ++t) {
        // ---- x[t, ebase+el, 0:10] ----
        float2 xv[2][5];
#pragma unroll
        for (int el = 0; el < 2; ++el) {
            const float2* xp = (const float2*)(x + ((size_t)t * BATCH + ebase + el) * 10);
#pragma unroll
            for (int i = 0; i < 5; ++i) xv[el][i] = xp[i];
        }

        // ---- Layer 1: 10 -> 64 (8 pairs per quarter, real inputs) ----
        u64 acc1[2][8];
#pragma unroll
        for (int el = 0; el < 2; ++el)
#pragma unroll
            for (int p = 0; p < 8; ++p) acc1[el][p] = 0ull;
#pragma unroll
        for (int i = 0; i < 10; ++i) {
            const ulonglong2* wp = (const ulonglong2*)(w1q + i * (4 * QS1));
            ulonglong2 wa = wp[0], wb = wp[1], wc = wp[2], wd = wp[3];
#pragma unroll
            for (int el = 0; el < 2; ++el) {
                float xf = (i & 1) ? xv[el][i >> 1].y : xv[el][i >> 1].x;
                u64 xd = pack2(xf, xf);
                acc1[el][0] = ffma2(xd, wa.x, acc1[el][0]);
                acc1[el][1] = ffma2(xd, wa.y, acc1[el][1]);
                acc1[el][2] = ffma2(xd, wb.x, acc1[el][2]);
                acc1[el][3] = ffma2(xd, wb.y, acc1[el][3]);
                acc1[el][4] = ffma2(xd, wc.x, acc1[el][4]);
                acc1[el][5] = ffma2(xd, wc.y, acc1[el][5]);
                acc1[el][6] = ffma2(xd, wd.x, acc1[el][6]);
                acc1[el][7] = ffma2(xd, wd.y, acc1[el][7]);
            }
        }
        // LIF + assemble 64-bit L1 spike mask (2 words) per element
        u32 l1lo[2], l1hi[2];
#pragma unroll
        for (int el = 0; el < 2; ++el) {
            u32 m16 = 0;
#pragma unroll
            for (int p = 0; p < 8; ++p)
                m16 |= lif_pair(acc1[el][p], m1[el][2 * p], m1[el][2 * p + 1]) << (2 * p);
            u32 w0 = (q < 2)  ? (m16 << (q * 16)) : 0u;
            u32 w1 = (q >= 2) ? (m16 << ((q - 2) * 16)) : 0u;
            l1lo[el] = bfly_or4(w0);
            l1hi[el] = bfly_or4(w1);
        }

        // ---- Layer 2: 64 -> 32 (4 pairs per quarter) ----
        u64 acc2[2][4];
#pragma unroll
        for (int el = 0; el < 2; ++el)
#pragma unroll
            for (int p = 0; p < 4; ++p) acc2[el][p] = 0ull;
#pragma unroll
        for (int i = 0; i < 64; ++i) {
            const ulonglong2* wp = (const ulonglong2*)(w2q + i * (4 * QS2));
            ulonglong2 wa = wp[0], wb = wp[1];
#pragma unroll
            for (int el = 0; el < 2; ++el) {
                u32 msk = (i < 32) ? l1lo[el] : l1hi[el];
                padd4(acc2[el][0], acc2[el][1], acc2[el][2], acc2[el][3],
                      msk, 1u << (i & 31), wa.x, wa.y, wb.x, wb.y);
            }
        }
        u32 f2[2];
#pragma unroll
        for (int el = 0; el < 2; ++el) {
            u32 m8 = 0;
#pragma unroll
            for (int p = 0; p < 4; ++p)
                m8 |= lif_pair(acc2[el][p], m2[el][2 * p], m2[el][2 * p + 1]) << (2 * p);
            f2[el] = bfly_or4(m8 << (q * 8));
        }

        // ---- Layer 3: 32 -> 32 ----
        u64 acc3[2][4];
#pragma unroll
        for (int el = 0; el < 2; ++el)
#pragma unroll
            for (int p = 0; p < 4; ++p) acc3[el][p] = 0ull;
#pragma unroll
        for (int i = 0; i < 32; ++i) {
            const ulonglong2* wp = (const ulonglong2*)(w3q + i * (4 * QS3));
            ulonglong2 wa = wp[0], wb = wp[1];
#pragma unroll
            for (int el = 0; el < 2; ++el)
                padd4(acc3[el][0], acc3[el][1], acc3[el][2], acc3[el][3],
                      f2[el], 1u << i, wa.x, wa.y, wb.x, wb.y);
        }
        u32 f3[2];
#pragma unroll
        for (int el = 0; el < 2; ++el) {
            u32 m8 = 0;
#pragma unroll
            for (int p = 0; p < 4; ++p)
                m8 |= lif_pair(acc3[el][p], m3[el][2 * p], m3[el][2 * p + 1]) << (2 * p);
            f3[el] = bfly_or4(m8 << (q * 8));
        }

        // ---- Layer 4: 32 -> 16 (2 pairs per quarter) ----
        u64 acc4[2][2];
#pragma unroll
        for (int el = 0; el < 2; ++el) { acc4[el][0] = 0ull; acc4[el][1] = 0ull; }
#pragma unroll
        for (int i = 0; i < 32; ++i) {
            const ulonglong2* wp = (const ulonglong2*)(w4q + i * (4 * QS4));
            ulonglong2 wa = wp[0];
#pragma unroll
            for (int el = 0; el < 2; ++el)
                padd2(acc4[el][0], acc4[el][1], f3[el], 1u << i, wa.x, wa.y);
        }
        u32 f4[2];
#pragma unroll
        for (int el = 0; el < 2; ++el) {
            u32 m4b = lif_pair(acc4[el][0], m4[el][0], m4[el][1])
                    | (lif_pair(acc4[el][1], m4[el][2], m4[el][3]) << 2);
            f4[el] = bfly_or4(m4b << (q * 4));
        }

        // ---- Layer 5: 16 -> 6 (padded to 8; 1 pair per quarter) ----
        u64 acc5[2];
        acc5[0] = 0ull; acc5[1] = 0ull;
#pragma unroll
        for (int i = 0; i < 16; ++i) {
            u64 w = w5q[i * (4 * QS5)];
#pragma unroll
            for (int el = 0; el < 2; ++el)
                padd1(acc5[el], f4[el], 1u << i, w);
        }
#pragma unroll
        for (int el = 0; el < 2; ++el) {
            float a0, a1; unpack2(acc5[el], a0, a1);
            float r0 = m5[el][0] > THRESHF ? THRESHF : 0.0f;
            float r1 = m5[el][1] > THRESHF ? THRESHF : 0.0f;
            float mm0 = fmaf(BETAF, m5[el][0], a0 - r0);
            float mm1 = fmaf(BETAF, m5[el][1], a1 - r1);
            m5[el][0] = mm0; m5[el][1] = mm1;
            if (q < 3) {
                float2 o;
                o.x = mm0 > THRESHF ? 1.0f : 0.0f;
                o.y = mm1 > THRESHF ? 1.0f : 0.0f;
                *(float2*)(out + ((size_t)t * BATCH + ebase + el) * 6 + q * 2) = o;
            }
        }
    }
}

extern "C" void kernel_launch(void* const* d_in, const int* in_sizes, int n_in,
                              void* d_out, int out_size) {
    const float *x = nullptr, *W1 = nullptr, *W2 = nullptr, *W3 = nullptr,
                *W4 = nullptr, *W5 = nullptr;
    for (int i = 0; i < n_in; ++i) {
        const float* p = (const float*)d_in[i];
        switch (in_sizes[i]) {
            case 52428800: x  = p; break;  // (20, 262144, 10)
            case 640:      W1 = p; break;  // (64, 10)
            case 2048:     W2 = p; break;  // (32, 64)
            case 1024:     W3 = p; break;  // (32, 32)
            case 512:      W4 = p; break;  // (16, 32)
            case 96:       W5 = p; break;  // (6, 16)
            default: break;
        }
    }
    float* out = (float*)d_out;
    // 4 threads per element, E=2 elements per thread: 64 elements per 128-thread block
    lif_kernel<<<BATCH / 64, 128>>>(x, W1, W2, W3, W4, W5, out);
}

// round 6
// speedup vs baseline: 1.6726x; 1.5622x over previous
#include <cuda_runtime.h>

#define BATCH   262144
#define T_STEPS 20
#define BETAF   0.9f
#define THRESHF 1.0f
#define E 2

using u32 = unsigned int;
using u64 = unsigned long long;

__device__ __forceinline__ u64 pack2(float lo, float hi) {
    u64 r; asm("mov.b64 %0, {%1, %2};" : "=l"(r) : "f"(lo), "f"(hi)); return r;
}
__device__ __forceinline__ void unpack2(u64 v, float &lo, float &hi) {
    asm("mov.b64 {%0, %1}, %2;" : "=f"(lo), "=f"(hi) : "l"(v));
}
// Packed dual fp32 FMA (2 MACs / instruction on the fma pipe)
__device__ __forceinline__ u64 ffma2(u64 a, u64 b, u64 c) {
    u64 d; asm("fma.rn.f32x2 %0, %1, %2, %3;" : "=l"(d) : "l"(a), "l"(b), "l"(c)); return d;
}

#define ONE2 0x3F8000003F800000ull

// ---- static smem weights, half-major pair-packed (round-3 layout: 2 distinct
// warp addresses per LDS -> broadcast-cheap) ----
// w[(i*2+half)*P2 + p] = (W[2*(half*P2+p)][i], W[2*(half*P2+p)+1][i])
__shared__ u64 sW1[10 * 2 * 16];  // 10 -> 64, P2=16
__shared__ u64 sW2[64 * 2 * 8];   // 64 -> 32, P2=8
__shared__ u64 sW3[32 * 2 * 8];   // 32 -> 32, P2=8
__shared__ u64 sW4[32 * 2 * 4];   // 32 -> 16, P2=4
__shared__ u64 sW5[16 * 2 * 2];   // 16 -> 6 (padded to 8), P2=2

__device__ __forceinline__ void stage(u64* dst, const float* __restrict__ W,
                                      int NIN, int NOUT, int P2, int tid, int nthr) {
    int total = NIN * 2 * P2;
    for (int idx = tid; idx < total; idx += nthr) {
        int i = idx / (2 * P2);
        int r = idx % (2 * P2);
        int h = r / P2, p = r % P2;
        int j0 = 2 * (h * P2 + p);
        float a = (j0     < NOUT) ? W[j0 * NIN + i]       : 0.0f;
        float b = (j0 + 1 < NOUT) ? W[(j0 + 1) * NIN + i] : 0.0f;
        dst[(i * 2 + h) * P2 + p] = pack2(a, b);
    }
}

// LIF for one output pair; returns 2-bit spike mask. Same formula/order as rounds 1-5.
__device__ __forceinline__ u32 lif_pair(u64 acc, float &mA, float &mB) {
    float a0, a1; unpack2(acc, a0, a1);
    float r0 = mA > THRESHF ? THRESHF : 0.0f;
    float r1 = mB > THRESHF ? THRESHF : 0.0f;
    mA = fmaf(BETAF, mA, a0 - r0);
    mB = fmaf(BETAF, mB, a1 - r1);
    u32 m = 0;
    if (mA > THRESHF) m |= 1u;
    if (mB > THRESHF) m |= 2u;
    return m;
}

__global__ __launch_bounds__(128) void lif_kernel(
    const float* __restrict__ x,
    const float* __restrict__ W1, const float* __restrict__ W2,
    const float* __restrict__ W3, const float* __restrict__ W4,
    const float* __restrict__ W5, float* __restrict__ out)
{
    int tid = threadIdx.x;
    stage(sW1, W1, 10, 64, 16, tid, 128);
    stage(sW2, W2, 64, 32,  8, tid, 128);
    stage(sW3, W3, 32, 32,  8, tid, 128);
    stage(sW4, W4, 32, 16,  4, tid, 128);
    stage(sW5, W5, 16,  6,  2, tid, 128);
    __syncthreads();

    const int half = tid & 1;                 // adjacent lanes = two halves of an element
    const size_t ebase = (size_t)blockIdx.x * 128 + (size_t)(tid >> 1) * E;

    // per-thread membrane state: half of every layer, for E elements
    float m1[E][32], m2[E][16], m3[E][16], m4[E][8], m5[E][4];
#pragma unroll
    for (int el = 0; el < E; ++el) {
#pragma unroll
        for (int k = 0; k < 32; ++k) m1[el][k] = 0.f;
#pragma unroll
        for (int k = 0; k < 16; ++k) { m2[el][k] = 0.f; m3[el][k] = 0.f; }
#pragma unroll
        for (int k = 0; k < 8; ++k)  m4[el][k] = 0.f;
#pragma unroll
        for (int k = 0; k < 4; ++k)  m5[el][k] = 0.f;
    }

#pragma unroll 1
    for (int t = 0; t < T_STEPS; ++t) {
        // ---- Layer 1: 10 -> 64, per element sequentially (caps live accs) ----
        u32 l1lo[E], l1hi[E];
#pragma unroll
        for (int el = 0; el < E; ++el) {
            const float2* xp = (const float2*)(x + ((size_t)t * BATCH + ebase + el) * 10);
            float2 xv[5];
#pragma unroll
            for (int i = 0; i < 5; ++i) xv[i] = xp[i];

            u64 acc1[16];
#pragma unroll
            for (int p = 0; p < 16; ++p) acc1[p] = 0ull;
#pragma unroll
            for (int i = 0; i < 10; ++i) {
                float xf = (i & 1) ? xv[i >> 1].y : xv[i >> 1].x;
                u64 xd = pack2(xf, xf);
                const ulonglong2* wp = (const ulonglong2*)(sW1 + (i * 2 + half) * 16);
#pragma unroll
                for (int p2 = 0; p2 < 8; ++p2) {
                    ulonglong2 w = wp[p2];
                    acc1[2 * p2]     = ffma2(xd, w.x, acc1[2 * p2]);
                    acc1[2 * p2 + 1] = ffma2(xd, w.y, acc1[2 * p2 + 1]);
                }
            }
            u32 msk = 0;
#pragma unroll
            for (int p = 0; p < 16; ++p)
                msk |= lif_pair(acc1[p], m1[el][2 * p], m1[el][2 * p + 1]) << (2 * p);
            u32 oth = __shfl_xor_sync(0xffffffffu, msk, 1);
            l1lo[el] = half ? oth : msk;          // L1 outputs 0..31
            l1hi[el] = half ? msk : oth;          // L1 outputs 32..63
        }

        // ---- Layer 2: 64 -> 32 (8 pairs per half), weights shared across E ----
        u64 acc2[E][8];
#pragma unroll
        for (int el = 0; el < E; ++el)
#pragma unroll
            for (int p = 0; p < 8; ++p) acc2[el][p] = 0ull;
#pragma unroll
        for (int i = 0; i < 64; ++i) {
            const ulonglong2* wp = (const ulonglong2*)(sW2 + (i * 2 + half) * 8);
            ulonglong2 wa = wp[0], wb = wp[1], wc = wp[2], wd = wp[3];
#pragma unroll
            for (int el = 0; el < E; ++el) {
                u32 msk = (i < 32) ? l1lo[el] : l1hi[el];
                u64 h2 = (msk & (1u << (i & 31))) ? ONE2 : 0ull;
                acc2[el][0] = ffma2(h2, wa.x, acc2[el][0]);
                acc2[el][1] = ffma2(h2, wa.y, acc2[el][1]);
                acc2[el][2] = ffma2(h2, wb.x, acc2[el][2]);
                acc2[el][3] = ffma2(h2, wb.y, acc2[el][3]);
                acc2[el][4] = ffma2(h2, wc.x, acc2[el][4]);
                acc2[el][5] = ffma2(h2, wc.y, acc2[el][5]);
                acc2[el][6] = ffma2(h2, wd.x, acc2[el][6]);
                acc2[el][7] = ffma2(h2, wd.y, acc2[el][7]);
            }
        }
        u32 f2[E];
#pragma unroll
        for (int el = 0; el < E; ++el) {
            u32 m16 = 0;
#pragma unroll
            for (int p = 0; p < 8; ++p)
                m16 |= lif_pair(acc2[el][p], m2[el][2 * p], m2[el][2 * p + 1]) << (2 * p);
            u32 oth = __shfl_xor_sync(0xffffffffu, m16, 1);
            f2[el] = half ? (oth | (m16 << 16)) : (m16 | (oth << 16));
        }

        // ---- Layer 3: 32 -> 32 ----
        u64 acc3[E][8];
#pragma unroll
        for (int el = 0; el < E; ++el)
#pragma unroll
            for (int p = 0; p < 8; ++p) acc3[el][p] = 0ull;
#pragma unroll
        for (int i = 0; i < 32; ++i) {
            const ulonglong2* wp = (const ulonglong2*)(sW3 + (i * 2 + half) * 8);
            ulonglong2 wa = wp[0], wb = wp[1], wc = wp[2], wd = wp[3];
#pragma unroll
            for (int el = 0; el < E; ++el) {
                u64 h2 = (f2[el] & (1u << i)) ? ONE2 : 0ull;
                acc3[el][0] = ffma2(h2, wa.x, acc3[el][0]);
                acc3[el][1] = ffma2(h2, wa.y, acc3[el][1]);
                acc3[el][2] = ffma2(h2, wb.x, acc3[el][2]);
                acc3[el][3] = ffma2(h2, wb.y, acc3[el][3]);
                acc3[el][4] = ffma2(h2, wc.x, acc3[el][4]);
                acc3[el][5] = ffma2(h2, wc.y, acc3[el][5]);
                acc3[el][6] = ffma2(h2, wd.x, acc3[el][6]);
                acc3[el][7] = ffma2(h2, wd.y, acc3[el][7]);
            }
        }
        u32 f3[E];
#pragma unroll
        for (int el = 0; el < E; ++el) {
            u32 m16 = 0;
#pragma unroll
            for (int p = 0; p < 8; ++p)
                m16 |= lif_pair(acc3[el][p], m3[el][2 * p], m3[el][2 * p + 1]) << (2 * p);
            u32 oth = __shfl_xor_sync(0xffffffffu, m16, 1);
            f3[el] = half ? (oth | (m16 << 16)) : (m16 | (oth << 16));
        }

        // ---- Layer 4: 32 -> 16 (4 pairs per half) ----
        u64 acc4[E][4];
#pragma unroll
        for (int el = 0; el < E; ++el)
#pragma unroll
            for (int p = 0; p < 4; ++p) acc4[el][p] = 0ull;
#pragma unroll
        for (int i = 0; i < 32; ++i) {
            const ulonglong2* wp = (const ulonglong2*)(sW4 + (i * 2 + half) * 4);
            ulonglong2 wa = wp[0], wb = wp[1];
#pragma unroll
            for (int el = 0; el < E; ++el) {
                u64 h2 = (f3[el] & (1u << i)) ? ONE2 : 0ull;
                acc4[el][0] = ffma2(h2, wa.x, acc4[el][0]);
                acc4[el][1] = ffma2(h2, wa.y, acc4[el][1]);
                acc4[el][2] = ffma2(h2, wb.x, acc4[el][2]);
                acc4[el][3] = ffma2(h2, wb.y, acc4[el][3]);
            }
        }
        u32 f4[E];
#pragma unroll
        for (int el = 0; el < E; ++el) {
            u32 m8 = 0;
#pragma unroll
            for (int p = 0; p < 4; ++p)
                m8 |= lif_pair(acc4[el][p], m4[el][2 * p], m4[el][2 * p + 1]) << (2 * p);
            u32 oth = __shfl_xor_sync(0xffffffffu, m8, 1);
            f4[el] = half ? (oth | (m8 << 8)) : (m8 | (oth << 8));
        }

        // ---- Layer 5: 16 -> 6 (padded to 8; 2 pairs per half) ----
        u64 acc5[E][2];
#pragma unroll
        for (int el = 0; el < E; ++el) { acc5[el][0] = 0ull; acc5[el][1] = 0ull; }
#pragma unroll
        for (int i = 0; i < 16; ++i) {
            const ulonglong2* wp = (const ulonglong2*)(sW5 + (i * 2 + half) * 2);
            ulonglong2 wa = wp[0];
#pragma unroll
            for (int el = 0; el < E; ++el) {
                u64 h2 = (f4[el] & (1u << i)) ? ONE2 : 0ull;
                acc5[el][0] = ffma2(h2, wa.x, acc5[el][0]);
                acc5[el][1] = ffma2(h2, wa.y, acc5[el][1]);
            }
        }
#pragma unroll
        for (int el = 0; el < E; ++el) {
            float s[4];
#pragma unroll
            for (int p = 0; p < 2; ++p) {
                float a0, a1; unpack2(acc5[el][p], a0, a1);
                float r0 = m5[el][2 * p]     > THRESHF ? THRESHF : 0.0f;
                float r1 = m5[el][2 * p + 1] > THRESHF ? THRESHF : 0.0f;
                float mm0 = fmaf(BETAF, m5[el][2 * p],     a0 - r0);
                float mm1 = fmaf(BETAF, m5[el][2 * p + 1], a1 - r1);
                m5[el][2 * p] = mm0; m5[el][2 * p + 1] = mm1;
                s[2 * p]     = mm0 > THRESHF ? 1.0f : 0.0f;
                s[2 * p + 1] = mm1 > THRESHF ? 1.0f : 0.0f;
            }
            // out[t, e, 0:6]: half0 -> neurons 0..3, half1 -> 4..5
            float* op = out + ((size_t)t * BATCH + ebase + el) * 6;
            if (!half) {
                *(float2*)(op)     = make_float2(s[0], s[1]);
                *(float2*)(op + 2) = make_float2(s[2], s[3]);
            } else {
                *(float2*)(op + 4) = make_float2(s[0], s[1]);
            }
        }
    }
}

extern "C" void kernel_launch(void* const* d_in, const int* in_sizes, int n_in,
                              void* d_out, int out_size) {
    const float *x = nullptr, *W1 = nullptr, *W2 = nullptr, *W3 = nullptr,
                *W4 = nullptr, *W5 = nullptr;
    for (int i = 0; i < n_in; ++i) {
        const float* p = (const float*)d_in[i];
        switch (in_sizes[i]) {
            case 52428800: x  = p; break;  // (20, 262144, 10)
            case 640:      W1 = p; break;  // (64, 10)
            case 2048:     W2 = p; break;  // (32, 64)
            case 1024:     W3 = p; break;  // (32, 32)
            case 512:      W4 = p; break;  // (16, 32)
            case 96:       W5 = p; break;  // (6, 16)
            default: break;
        }
    }
    float* out = (float*)d_out;
    // 2 threads per element, E=2 elements per thread: 128 elements per 128-thread block
    lif_kernel<<<BATCH / 128, 128>>>(x, W1, W2, W3, W4, W5, out);
}